// round 12
// baseline (speedup 1.0000x reference)
#include <cuda_runtime.h>
#include <cuda_bf16.h>
#include <math.h>

// ---------------------------------------------------------------------------
// Problem constants
// ---------------------------------------------------------------------------
#define BB     4
#define TT     2048
#define DM     256
#define DFF    1024
#define NH     4
#define DK     64
#define BT     (BB*TT)          // 8192 rows

// ---------------------------------------------------------------------------
// Scratch
// ---------------------------------------------------------------------------
__device__ __nv_bfloat16 gb_h   [BT*DM];
__device__ __nv_bfloat16 gb_q   [BT*DM];
__device__ __nv_bfloat16 gb_k   [BT*DM];
__device__ __nv_bfloat16 gb_v   [BT*DM];
__device__ __nv_bfloat16 gb_attn[BT*DM];
__device__ __nv_bfloat16 gb_hf  [BT*DM];
__device__ __nv_bfloat16 gb_gate[BT*DFF];
__device__ float         g_x1   [BT*DM];
// bf16 weights
__device__ __nv_bfloat16 gb_wq[DM*DM];
__device__ __nv_bfloat16 gb_wk[DM*DM];
__device__ __nv_bfloat16 gb_wv[DM*DM];
__device__ __nv_bfloat16 gb_wo[DM*DM];
__device__ __nv_bfloat16 gb_wg[DFF*DM];
__device__ __nv_bfloat16 gb_wu[DFF*DM];
__device__ __nv_bfloat16 gb_wd[DM*DFF];

// ---------------------------------------------------------------------------
// helpers
// ---------------------------------------------------------------------------
__device__ __forceinline__ void mma_bf16(float* c, const unsigned* a, const unsigned* b) {
    asm volatile(
        "mma.sync.aligned.m16n8k16.row.col.f32.bf16.bf16.f32 "
        "{%0,%1,%2,%3}, {%4,%5,%6,%7}, {%8,%9}, {%0,%1,%2,%3};\n"
        : "+f"(c[0]), "+f"(c[1]), "+f"(c[2]), "+f"(c[3])
        : "r"(a[0]), "r"(a[1]), "r"(a[2]), "r"(a[3]), "r"(b[0]), "r"(b[1]));
}

__device__ __forceinline__ void ldsm4(unsigned* r, const __nv_bfloat16* p) {
    unsigned a = (unsigned)__cvta_generic_to_shared(p);
    asm volatile("ldmatrix.sync.aligned.m8n8.x4.shared.b16 {%0,%1,%2,%3}, [%4];"
                 : "=r"(r[0]), "=r"(r[1]), "=r"(r[2]), "=r"(r[3]) : "r"(a));
}
__device__ __forceinline__ void ldsm4t(unsigned* r, const __nv_bfloat16* p) {
    unsigned a = (unsigned)__cvta_generic_to_shared(p);
    asm volatile("ldmatrix.sync.aligned.m8n8.x4.trans.shared.b16 {%0,%1,%2,%3}, [%4];"
                 : "=r"(r[0]), "=r"(r[1]), "=r"(r[2]), "=r"(r[3]) : "r"(a));
}

__device__ __forceinline__ unsigned pack_bf16(float lo, float hi) {
    unsigned r;
    asm("cvt.rn.bf16x2.f32 %0, %1, %2;" : "=r"(r) : "f"(hi), "f"(lo));
    return r;
}

__device__ __forceinline__ void cpa16(void* s, const void* g) {
    unsigned sa = (unsigned)__cvta_generic_to_shared(s);
    asm volatile("cp.async.cg.shared.global [%0], [%1], 16;" :: "r"(sa), "l"(g));
}
__device__ __forceinline__ void cp_commit() { asm volatile("cp.async.commit_group;"); }
template<int N> __device__ __forceinline__ void cp_wait() {
    asm volatile("cp.async.wait_group %0;" :: "n"(N));
}

// ---------------------------------------------------------------------------
// Weight conversion fp32 -> bf16 (4 tensors per launch; grid.y selects)
// ---------------------------------------------------------------------------
__global__ void conv4(const float* s0, const float* s1, const float* s2, const float* s3,
                      __nv_bfloat16* d0, __nv_bfloat16* d1, __nv_bfloat16* d2,
                      __nv_bfloat16* d3) {
    const float* s = (blockIdx.y == 0) ? s0 : (blockIdx.y == 1) ? s1 : (blockIdx.y == 2) ? s2 : s3;
    __nv_bfloat16* d = (blockIdx.y == 0) ? d0 : (blockIdx.y == 1) ? d1 : (blockIdx.y == 2) ? d2 : d3;
    int i = blockIdx.x*blockDim.x + threadIdx.x;
    float4 v = ((const float4*)s)[i];
    __nv_bfloat162* d2p = (__nv_bfloat162*)d;
    d2p[2*i]   = __floats2bfloat162_rn(v.x, v.y);
    d2p[2*i+1] = __floats2bfloat162_rn(v.z, v.w);
}

// ---------------------------------------------------------------------------
// RMSNorm -> bf16 out
// ---------------------------------------------------------------------------
__global__ void rmsnorm_kernel(__nv_bfloat16* __restrict__ out, const float* __restrict__ x,
                               const float* __restrict__ w) {
    int row = blockIdx.x;
    int tid = threadIdx.x;
    float vx = x[row*DM + tid];
    float ss = vx*vx;
    #pragma unroll
    for (int off = 16; off >= 1; off >>= 1) ss += __shfl_xor_sync(0xffffffffu, ss, off);
    __shared__ float ws[8];
    if ((tid & 31) == 0) ws[tid >> 5] = ss;
    __syncthreads();
    float tot = ws[0];
    #pragma unroll
    for (int i = 1; i < 8; ++i) tot += ws[i];
    float rinv = rsqrtf(tot * (1.0f/DM) + 1e-5f);
    out[row*DM + tid] = __float2bfloat16_rn(vx * rinv * w[tid]);
}

// ---------------------------------------------------------------------------
// bf16 tensor-core GEMM: C[M,N] = A[M,K] @ Bw[N,K]^T (+res if fp32 out)
// 128 x BN_ tile, BK=64, 3-stage cp.async, 8 warps (4x2), ldmatrix b16
// OBF: true -> bf16 output (no residual), false -> fp32 output (+res)
// ---------------------------------------------------------------------------
#define TSTR 72   // bf16 units per smem row (64 + 8 pad)

template<int BN_, bool OBF>
__global__ __launch_bounds__(256, 2)
void gemm_bf16(const __nv_bfloat16* __restrict__ A,
               const __nv_bfloat16* __restrict__ B0, const __nv_bfloat16* __restrict__ B1,
               const __nv_bfloat16* __restrict__ B2,
               void* __restrict__ C0, void* __restrict__ C1, void* __restrict__ C2,
               const float* __restrict__ res,
               int M, int N, int K) {
    constexpr int WN  = BN_/16;
    constexpr int ASZ = 128*TSTR;
    constexpr int BSZ = BN_*TSTR;
    extern __shared__ __nv_bfloat16 smb[];
    __nv_bfloat16* As = smb;                  // 3 stages
    __nv_bfloat16* Bs = smb + 3*ASZ;

    const __nv_bfloat16* Bw = (blockIdx.z == 0) ? B0 : (blockIdx.z == 1 ? B1 : B2);
    void*                C  = (blockIdx.z == 0) ? C0 : (blockIdx.z == 1 ? C1 : C2);

    const int tid = threadIdx.x, lane = tid & 31, wid = tid >> 5;
    const int wrow = wid >> 1, wcol = wid & 1;
    const int row0 = blockIdx.y * 128;
    const int col0 = blockIdx.x * BN_;

    const int aoff = ((lane & 7) + ((lane >> 3) & 1)*8)*TSTR + (lane >> 4)*8;
    const int boff = ((lane & 7) + (lane >> 4)*8)*TSTR + ((lane >> 3) & 1)*8;

    float acc[2][WN][4];
    #pragma unroll
    for (int i = 0; i < 2; ++i)
        #pragma unroll
        for (int j = 0; j < WN; ++j)
            #pragma unroll
            for (int t = 0; t < 4; ++t) acc[i][j][t] = 0.f;

    auto load_stage = [&](int k0, int st) {
        __nv_bfloat16* as = As + st*ASZ;
        __nv_bfloat16* bs = Bs + st*BSZ;
        #pragma unroll
        for (int it = 0; it < 4; ++it) {
            int idx = it*256 + tid, r = idx >> 3, c8 = (idx & 7)*8;
            cpa16(as + r*TSTR + c8, A + (size_t)(row0 + r)*K + k0 + c8);
        }
        #pragma unroll
        for (int it = 0; it < BN_/32; ++it) {
            int idx = it*256 + tid, r = idx >> 3, c8 = (idx & 7)*8;
            cpa16(bs + r*TSTR + c8, Bw + (size_t)(col0 + r)*K + k0 + c8);
        }
        cp_commit();
    };

    const int nt = K / 64;
    load_stage(0, 0);
    load_stage(64, 1);
    for (int t = 0; t < nt; ++t) {
        if (t + 2 < nt)      { load_stage((t+2)*64, (t+2) % 3); cp_wait<2>(); }
        else if (t + 1 < nt) { cp_wait<1>(); }
        else                 { cp_wait<0>(); }
        __syncthreads();
        const __nv_bfloat16* as = As + (t % 3)*ASZ + aoff + wrow*32*TSTR;
        const __nv_bfloat16* bs = Bs + (t % 3)*BSZ + boff + wcol*(BN_/2)*TSTR;
        #pragma unroll
        for (int ks = 0; ks < 4; ++ks) {
            const int kk = ks*16;
            unsigned a[2][4], b[WN][2];
            #pragma unroll
            for (int i = 0; i < 2; ++i)
                ldsm4(a[i], as + i*16*TSTR + kk);
            #pragma unroll
            for (int jp = 0; jp < WN/2; ++jp)
                ldsm4(&b[2*jp][0], bs + jp*16*TSTR + kk);
            #pragma unroll
            for (int i = 0; i < 2; ++i)
                #pragma unroll
                for (int j = 0; j < WN; ++j)
                    mma_bf16(acc[i][j], a[i], b[j]);
        }
        __syncthreads();
    }

    #pragma unroll
    for (int i = 0; i < 2; ++i) {
        int r = row0 + wrow*32 + i*16 + (lane >> 2);
        #pragma unroll
        for (int j = 0; j < WN; ++j) {
            int c = col0 + wcol*(BN_/2) + j*8 + (lane & 3)*2;
            if (OBF) {
                __nv_bfloat16* Cb = (__nv_bfloat16*)C;
                *(unsigned*)(Cb + (size_t)r*N + c)     = pack_bf16(acc[i][j][0], acc[i][j][1]);
                *(unsigned*)(Cb + (size_t)(r+8)*N + c) = pack_bf16(acc[i][j][2], acc[i][j][3]);
            } else {
                float* Cf = (float*)C;
                float2 v01 = { acc[i][j][0], acc[i][j][1] };
                float2 v23 = { acc[i][j][2], acc[i][j][3] };
                if (res) {
                    float2 r01 = *(const float2*)(res + (size_t)r*N + c);
                    float2 r23 = *(const float2*)(res + (size_t)(r+8)*N + c);
                    v01.x += r01.x; v01.y += r01.y;
                    v23.x += r23.x; v23.y += r23.y;
                }
                *(float2*)(Cf + (size_t)r*N + c)     = v01;
                *(float2*)(Cf + (size_t)(r+8)*N + c) = v23;
            }
        }
    }
}

// ---------------------------------------------------------------------------
// Fused gate/up GEMM + SiLU (bf16): g = silu(A@Wg^T) * (A@Wu^T), bf16 out
// ---------------------------------------------------------------------------
__global__ __launch_bounds__(256, 2)
void gemm_gateup(const __nv_bfloat16* __restrict__ A,
                 const __nv_bfloat16* __restrict__ Wg, const __nv_bfloat16* __restrict__ Wu,
                 __nv_bfloat16* __restrict__ G, int M, int N, int K) {
    constexpr int ASZ = 128*TSTR;
    constexpr int BSZ = 64*TSTR;
    extern __shared__ __nv_bfloat16 smb[];
    __nv_bfloat16* As = smb;
    __nv_bfloat16* Gs = smb + 3*ASZ;
    __nv_bfloat16* Us = Gs + 3*BSZ;

    const int tid = threadIdx.x, lane = tid & 31, wid = tid >> 5;
    const int wrow = wid >> 1, wcol = wid & 1;
    const int row0 = blockIdx.y * 128;
    const int col0 = blockIdx.x * 64;

    const int aoff = ((lane & 7) + ((lane >> 3) & 1)*8)*TSTR + (lane >> 4)*8;
    const int boff = ((lane & 7) + (lane >> 4)*8)*TSTR + ((lane >> 3) & 1)*8;

    float accg[2][4][4], accu[2][4][4];
    #pragma unroll
    for (int i = 0; i < 2; ++i)
        #pragma unroll
        for (int j = 0; j < 4; ++j)
            #pragma unroll
            for (int t = 0; t < 4; ++t) { accg[i][j][t] = 0.f; accu[i][j][t] = 0.f; }

    auto load_stage = [&](int k0, int st) {
        __nv_bfloat16* as = As + st*ASZ;
        __nv_bfloat16* gs = Gs + st*BSZ;
        __nv_bfloat16* us = Us + st*BSZ;
        #pragma unroll
        for (int it = 0; it < 4; ++it) {
            int idx = it*256 + tid, r = idx >> 3, c8 = (idx & 7)*8;
            cpa16(as + r*TSTR + c8, A + (size_t)(row0 + r)*K + k0 + c8);
        }
        #pragma unroll
        for (int it = 0; it < 2; ++it) {
            int idx = it*256 + tid, r = idx >> 3, c8 = (idx & 7)*8;
            cpa16(gs + r*TSTR + c8, Wg + (size_t)(col0 + r)*K + k0 + c8);
            cpa16(us + r*TSTR + c8, Wu + (size_t)(col0 + r)*K + k0 + c8);
        }
        cp_commit();
    };

    const int nt = K / 64;
    load_stage(0, 0);
    load_stage(64, 1);
    for (int t = 0; t < nt; ++t) {
        if (t + 2 < nt)      { load_stage((t+2)*64, (t+2) % 3); cp_wait<2>(); }
        else if (t + 1 < nt) { cp_wait<1>(); }
        else                 { cp_wait<0>(); }
        __syncthreads();
        const __nv_bfloat16* as = As + (t % 3)*ASZ + aoff + wrow*32*TSTR;
        const __nv_bfloat16* gs = Gs + (t % 3)*BSZ + boff + wcol*32*TSTR;
        const __nv_bfloat16* us = Us + (t % 3)*BSZ + boff + wcol*32*TSTR;
        #pragma unroll
        for (int ks = 0; ks < 4; ++ks) {
            const int kk = ks*16;
            unsigned a[2][4], bg[4][2], bu[4][2];
            #pragma unroll
            for (int i = 0; i < 2; ++i)
                ldsm4(a[i], as + i*16*TSTR + kk);
            #pragma unroll
            for (int jp = 0; jp < 2; ++jp) {
                ldsm4(&bg[2*jp][0], gs + jp*16*TSTR + kk);
                ldsm4(&bu[2*jp][0], us + jp*16*TSTR + kk);
            }
            #pragma unroll
            for (int i = 0; i < 2; ++i)
                #pragma unroll
                for (int j = 0; j < 4; ++j) {
                    mma_bf16(accg[i][j], a[i], bg[j]);
                    mma_bf16(accu[i][j], a[i], bu[j]);
                }
        }
        __syncthreads();
    }

    #pragma unroll
    for (int i = 0; i < 2; ++i) {
        int r = row0 + wrow*32 + i*16 + (lane >> 2);
        #pragma unroll
        for (int j = 0; j < 4; ++j) {
            int c = col0 + wcol*32 + j*8 + (lane & 3)*2;
            float g0 = accg[i][j][0], g1 = accg[i][j][1];
            float g2 = accg[i][j][2], g3 = accg[i][j][3];
            float p0 = g0 / (1.f + __expf(-g0)) * accu[i][j][0];
            float p1 = g1 / (1.f + __expf(-g1)) * accu[i][j][1];
            float p2 = g2 / (1.f + __expf(-g2)) * accu[i][j][2];
            float p3 = g3 / (1.f + __expf(-g3)) * accu[i][j][3];
            *(unsigned*)(G + (size_t)r*N + c)     = pack_bf16(p0, p1);
            *(unsigned*)(G + (size_t)(r+8)*N + c) = pack_bf16(p2, p3);
        }
    }
}

// ---------------------------------------------------------------------------
// bf16 tensor-core flash attention, double-buffered K/V, occ 4
// 512 blocks (16 bh x 32 q-tiles of 64 rows, heavy-first), 128 threads
// ---------------------------------------------------------------------------
#define QSTR 72
#define KSTR 72
#define VSTR 72

__global__ __launch_bounds__(128, 4)
void attn_bf16(__nv_bfloat16* __restrict__ out, const __nv_bfloat16* __restrict__ q,
               const __nv_bfloat16* __restrict__ k, const __nv_bfloat16* __restrict__ v) {
    extern __shared__ __nv_bfloat16 smb[];
    __nv_bfloat16* Qs = smb;                    // 64 x QSTR
    __nv_bfloat16* Ks = Qs + 64*QSTR;           // 2 stages 64 x KSTR
    __nv_bfloat16* Vs = Ks + 2*64*KSTR;         // 2 stages 64 x VSTR

    const int tid = threadIdx.x, lane = tid & 31, wid = tid >> 5;
    const int bh = blockIdx.x;
    const int qx = 31 - blockIdx.y;             // heavy tiles first
    const int b = bh >> 2, h = bh & 3;
    const int q0 = qx * 64;
    const int ntile = qx + 1;
    const size_t base = (size_t)b*TT*DM + (size_t)h*DK;

    const int r0l = wid*16 + (lane >> 2);
    const float sc = 0.125f;

    // ldmatrix lane offsets (A-pattern also serves V-trans)
    const int aoff = ((lane & 7) + ((lane >> 3) & 1)*8)*QSTR + (lane >> 4)*8;
    const int koff = ((lane & 7) + (lane >> 4)*8)*KSTR + ((lane >> 3) & 1)*8;
    const int voff = ((lane & 7) + ((lane >> 3) & 1)*8)*VSTR + (lane >> 4)*8;

    auto load_kv = [&](int jt, int st) {
        const int k0 = jt*64;
        __nv_bfloat16* ks_ = Ks + st*64*KSTR;
        __nv_bfloat16* vs_ = Vs + st*64*VSTR;
        #pragma unroll
        for (int it = 0; it < 4; ++it) {
            int idx = it*128 + tid, r = idx >> 3, c8 = (idx & 7)*8;
            cpa16(ks_ + r*KSTR + c8, k + base + (size_t)(k0 + r)*DM + c8);
            cpa16(vs_ + r*VSTR + c8, v + base + (size_t)(k0 + r)*DM + c8);
        }
        cp_commit();
    };

    // Q tile + first KV stage
    #pragma unroll
    for (int it = 0; it < 4; ++it) {
        int idx = it*128 + tid, r = idx >> 3, c8 = (idx & 7)*8;
        cpa16(Qs + r*QSTR + c8, q + base + (size_t)(q0 + r)*DM + c8);
    }
    cp_commit();
    load_kv(0, 0);

    float o[8][4];
    #pragma unroll
    for (int j = 0; j < 8; ++j)
        #pragma unroll
        for (int t = 0; t < 4; ++t) o[j][t] = 0.f;
    float m0 = -1e30f, m1 = -1e30f, l0 = 0.f, l1 = 0.f;

    for (int jt = 0; jt < ntile; ++jt) {
        if (jt + 1 < ntile) { load_kv(jt+1, (jt+1) & 1); cp_wait<1>(); }
        else                { cp_wait<0>(); }
        __syncthreads();
        const __nv_bfloat16* ks_ = Ks + (jt & 1)*64*KSTR;
        const __nv_bfloat16* vs_ = Vs + (jt & 1)*64*VSTR;
        const int k0 = jt*64;

        // ---- S = Q @ K^T : 4 k16 steps, 8 n-tiles ----
        float s[8][4];
        #pragma unroll
        for (int j = 0; j < 8; ++j)
            #pragma unroll
            for (int t = 0; t < 4; ++t) s[j][t] = 0.f;
        #pragma unroll
        for (int ks = 0; ks < 4; ++ks) {
            const int kk = ks*16;
            unsigned aq[4], bv[8][2];
            ldsm4(aq, Qs + wid*16*QSTR + aoff + kk);
            #pragma unroll
            for (int jp = 0; jp < 4; ++jp)
                ldsm4(&bv[2*jp][0], ks_ + jp*16*KSTR + koff + kk);
            #pragma unroll
            for (int j = 0; j < 8; ++j)
                mma_bf16(s[j], aq, bv[j]);
        }

        // ---- causal mask (diagonal tile only) ----
        if (jt == ntile - 1) {
            const int row_a = q0 + r0l, row_b = row_a + 8;
            #pragma unroll
            for (int j = 0; j < 8; ++j) {
                int col = k0 + j*8 + 2*(lane & 3);
                if (col     > row_a) s[j][0] = -1e30f;
                if (col + 1 > row_a) s[j][1] = -1e30f;
                if (col     > row_b) s[j][2] = -1e30f;
                if (col + 1 > row_b) s[j][3] = -1e30f;
            }
        }

        // ---- online softmax ----
        float mx0 = -1e30f, mx1 = -1e30f;
        #pragma unroll
        for (int j = 0; j < 8; ++j) {
            mx0 = fmaxf(mx0, fmaxf(s[j][0], s[j][1]));
            mx1 = fmaxf(mx1, fmaxf(s[j][2], s[j][3]));
        }
        #pragma unroll
        for (int off = 1; off <= 2; off <<= 1) {
            mx0 = fmaxf(mx0, __shfl_xor_sync(0xffffffffu, mx0, off));
            mx1 = fmaxf(mx1, __shfl_xor_sync(0xffffffffu, mx1, off));
        }
        float mn0 = fmaxf(m0, mx0), mn1 = fmaxf(m1, mx1);
        float al0 = __expf((m0 - mn0)*sc), al1 = __expf((m1 - mn1)*sc);
        m0 = mn0; m1 = mn1;
        float rs0 = 0.f, rs1 = 0.f;
        #pragma unroll
        for (int j = 0; j < 8; ++j) {
            s[j][0] = __expf((s[j][0] - mn0)*sc); rs0 += s[j][0];
            s[j][1] = __expf((s[j][1] - mn0)*sc); rs0 += s[j][1];
            s[j][2] = __expf((s[j][2] - mn1)*sc); rs1 += s[j][2];
            s[j][3] = __expf((s[j][3] - mn1)*sc); rs1 += s[j][3];
        }
        #pragma unroll
        for (int off = 1; off <= 2; off <<= 1) {
            rs0 += __shfl_xor_sync(0xffffffffu, rs0, off);
            rs1 += __shfl_xor_sync(0xffffffffu, rs1, off);
        }
        l0 = l0*al0 + rs0;
        l1 = l1*al1 + rs1;

        // ---- O = O*alpha + P @ V (P packs directly to bf16 A-fragments) ----
        #pragma unroll
        for (int j = 0; j < 8; ++j) {
            o[j][0] *= al0; o[j][1] *= al0;
            o[j][2] *= al1; o[j][3] *= al1;
        }
        #pragma unroll
        for (int kb = 0; kb < 4; ++kb) {
            unsigned ap[4];
            ap[0] = pack_bf16(s[2*kb  ][0], s[2*kb  ][1]);
            ap[1] = pack_bf16(s[2*kb  ][2], s[2*kb  ][3]);
            ap[2] = pack_bf16(s[2*kb+1][0], s[2*kb+1][1]);
            ap[3] = pack_bf16(s[2*kb+1][2], s[2*kb+1][3]);
            const int kk = kb*16;
            unsigned bv[8][2];
            #pragma unroll
            for (int jp = 0; jp < 4; ++jp)
                ldsm4t(&bv[2*jp][0], vs_ + kk*VSTR + voff + jp*16);
            #pragma unroll
            for (int j = 0; j < 8; ++j)
                mma_bf16(o[j], ap, bv[j]);
        }
        __syncthreads();                // all reads of this stage done
    }

    // ---- epilogue (bf16 out) ----
    const float inv0 = 1.f / l0, inv1 = 1.f / l1;
    const int grow = q0 + r0l;
    #pragma unroll
    for (int j = 0; j < 8; ++j) {
        int cc = j*8 + 2*(lane & 3);
        *(unsigned*)(out + base + (size_t)grow*DM + cc) =
            pack_bf16(o[j][0]*inv0, o[j][1]*inv0);
        *(unsigned*)(out + base + (size_t)(grow + 8)*DM + cc) =
            pack_bf16(o[j][2]*inv1, o[j][3]*inv1);
    }
}

// ---------------------------------------------------------------------------
// Launch
// ---------------------------------------------------------------------------
extern "C" void kernel_launch(void* const* d_in, const int* in_sizes, int n_in,
                              void* d_out, int out_size) {
    const float* x        = (const float*)d_in[0];
    const float* rms_attn = (const float*)d_in[2];
    const float* wq       = (const float*)d_in[3];
    const float* wk       = (const float*)d_in[4];
    const float* wv       = (const float*)d_in[5];
    const float* wo       = (const float*)d_in[6];
    const float* rms_ffn  = (const float*)d_in[7];
    const float* w_gate   = (const float*)d_in[8];
    const float* w_up     = (const float*)d_in[9];
    const float* w_down   = (const float*)d_in[10];
    float* out = (float*)d_out;

    __nv_bfloat16 *h, *q, *k, *v, *attn, *hf, *gate;
    __nv_bfloat16 *bwq, *bwk, *bwv, *bwo, *bwg, *bwu, *bwd;
    float *x1;
    cudaGetSymbolAddress((void**)&h,    gb_h);
    cudaGetSymbolAddress((void**)&q,    gb_q);
    cudaGetSymbolAddress((void**)&k,    gb_k);
    cudaGetSymbolAddress((void**)&v,    gb_v);
    cudaGetSymbolAddress((void**)&attn, gb_attn);
    cudaGetSymbolAddress((void**)&hf,   gb_hf);
    cudaGetSymbolAddress((void**)&gate, gb_gate);
    cudaGetSymbolAddress((void**)&x1,   g_x1);
    cudaGetSymbolAddress((void**)&bwq,  gb_wq);
    cudaGetSymbolAddress((void**)&bwk,  gb_wk);
    cudaGetSymbolAddress((void**)&bwv,  gb_wv);
    cudaGetSymbolAddress((void**)&bwo,  gb_wo);
    cudaGetSymbolAddress((void**)&bwg,  gb_wg);
    cudaGetSymbolAddress((void**)&bwu,  gb_wu);
    cudaGetSymbolAddress((void**)&bwd,  gb_wd);

    const int GS128 = 3*(128 + 128)*TSTR*2;                 // 110592 B
    const int GS64  = 3*(128 +  64)*TSTR*2;                 // 82944 B
    const int GSGU  = 3*(128 + 64 + 64)*TSTR*2;             // 110592 B
    const int ASM   = (64*QSTR + 2*64*KSTR + 2*64*VSTR)*2;  // 46080 B
    cudaFuncSetAttribute((const void*)gemm_bf16<128,true>,  cudaFuncAttributeMaxDynamicSharedMemorySize, GS128);
    cudaFuncSetAttribute((const void*)gemm_bf16<64,false>,  cudaFuncAttributeMaxDynamicSharedMemorySize, GS64);
    cudaFuncSetAttribute((const void*)gemm_gateup,          cudaFuncAttributeMaxDynamicSharedMemorySize, GSGU);
    cudaFuncSetAttribute((const void*)attn_bf16,            cudaFuncAttributeMaxDynamicSharedMemorySize, ASM);

    // 0. convert weights to bf16
    conv4<<<dim3(DM*DM/1024, 4), 256>>>(wq, wk, wv, wo, bwq, bwk, bwv, bwo);
    conv4<<<dim3(DFF*DM/1024, 3), 256>>>(w_gate, w_up, w_down, w_down, bwg, bwu, bwd, bwd);

    // 1. h = rmsnorm(x) -> bf16
    rmsnorm_kernel<<<BT, 256>>>(h, x, rms_attn);

    // 2. fused q,k,v projections -> bf16
    gemm_bf16<128,true><<<dim3(DM/128, BT/128, 3), 256, GS128>>>(
        h, bwq, bwk, bwv, q, k, v, nullptr, BT, DM, DM);

    // 3. attention -> bf16
    attn_bf16<<<dim3(BB*NH, 32), 128, ASM>>>(attn, q, k, v);

    // 4. x1 = x + attn @ wo^T  (fp32)
    gemm_bf16<64,false><<<dim3(DM/64, BT/128, 1), 256, GS64>>>(
        attn, bwo, bwo, bwo, x1, x1, x1, x, BT, DM, DM);

    // 5. hf = rmsnorm(x1) -> bf16
    rmsnorm_kernel<<<BT, 256>>>(hf, x1, rms_ffn);

    // 6. fused gate/up/silu -> bf16
    gemm_gateup<<<dim3(DFF/64, BT/128), 256, GSGU>>>(
        hf, bwg, bwu, gate, BT, DFF, DM);

    // 7. out = x1 + gate @ w_down^T  (fp32)
    gemm_bf16<64,false><<<dim3(DM/64, BT/128, 1), 256, GS64>>>(
        gate, bwd, bwd, bwd, out, out, out, x1, BT, DM, DFF);
}

// round 13
// speedup vs baseline: 1.0016x; 1.0016x over previous
#include <cuda_runtime.h>
#include <cuda_bf16.h>
#include <math.h>

// ---------------------------------------------------------------------------
// Problem constants
// ---------------------------------------------------------------------------
#define BB     4
#define TT     2048
#define DM     256
#define DFF    1024
#define NH     4
#define DK     64
#define BT     (BB*TT)          // 8192 rows

// ---------------------------------------------------------------------------
// Scratch
// ---------------------------------------------------------------------------
__device__ __nv_bfloat16 gb_h   [BT*DM];
__device__ __nv_bfloat16 gb_q   [BT*DM];
__device__ __nv_bfloat16 gb_k   [BT*DM];
__device__ __nv_bfloat16 gb_v   [BT*DM];
__device__ __nv_bfloat16 gb_attn[BT*DM];
__device__ __nv_bfloat16 gb_hf  [BT*DM];
__device__ __nv_bfloat16 gb_gate[BT*DFF];
__device__ float         g_x1   [BT*DM];
// bf16 weights
__device__ __nv_bfloat16 gb_wq[DM*DM];
__device__ __nv_bfloat16 gb_wk[DM*DM];
__device__ __nv_bfloat16 gb_wv[DM*DM];
__device__ __nv_bfloat16 gb_wo[DM*DM];
__device__ __nv_bfloat16 gb_wg[DFF*DM];
__device__ __nv_bfloat16 gb_wu[DFF*DM];
__device__ __nv_bfloat16 gb_wd[DM*DFF];

// ---------------------------------------------------------------------------
// helpers
// ---------------------------------------------------------------------------
__device__ __forceinline__ void mma_bf16(float* c, const unsigned* a, const unsigned* b) {
    asm volatile(
        "mma.sync.aligned.m16n8k16.row.col.f32.bf16.bf16.f32 "
        "{%0,%1,%2,%3}, {%4,%5,%6,%7}, {%8,%9}, {%0,%1,%2,%3};\n"
        : "+f"(c[0]), "+f"(c[1]), "+f"(c[2]), "+f"(c[3])
        : "r"(a[0]), "r"(a[1]), "r"(a[2]), "r"(a[3]), "r"(b[0]), "r"(b[1]));
}

__device__ __forceinline__ void ldsm4(unsigned* r, const __nv_bfloat16* p) {
    unsigned a = (unsigned)__cvta_generic_to_shared(p);
    asm volatile("ldmatrix.sync.aligned.m8n8.x4.shared.b16 {%0,%1,%2,%3}, [%4];"
                 : "=r"(r[0]), "=r"(r[1]), "=r"(r[2]), "=r"(r[3]) : "r"(a));
}
__device__ __forceinline__ void ldsm4t(unsigned* r, const __nv_bfloat16* p) {
    unsigned a = (unsigned)__cvta_generic_to_shared(p);
    asm volatile("ldmatrix.sync.aligned.m8n8.x4.trans.shared.b16 {%0,%1,%2,%3}, [%4];"
                 : "=r"(r[0]), "=r"(r[1]), "=r"(r[2]), "=r"(r[3]) : "r"(a));
}

__device__ __forceinline__ unsigned pack_bf16(float lo, float hi) {
    unsigned r;
    asm("cvt.rn.bf16x2.f32 %0, %1, %2;" : "=r"(r) : "f"(hi), "f"(lo));
    return r;
}

__device__ __forceinline__ void cpa16(void* s, const void* g) {
    unsigned sa = (unsigned)__cvta_generic_to_shared(s);
    asm volatile("cp.async.cg.shared.global [%0], [%1], 16;" :: "r"(sa), "l"(g));
}
__device__ __forceinline__ void cp_commit() { asm volatile("cp.async.commit_group;"); }
template<int N> __device__ __forceinline__ void cp_wait() {
    asm volatile("cp.async.wait_group %0;" :: "n"(N));
}

// ---------------------------------------------------------------------------
// Weight conversion fp32 -> bf16 (4 tensors per launch; grid.y selects)
// ---------------------------------------------------------------------------
__global__ void conv4(const float* s0, const float* s1, const float* s2, const float* s3,
                      __nv_bfloat16* d0, __nv_bfloat16* d1, __nv_bfloat16* d2,
                      __nv_bfloat16* d3) {
    const float* s = (blockIdx.y == 0) ? s0 : (blockIdx.y == 1) ? s1 : (blockIdx.y == 2) ? s2 : s3;
    __nv_bfloat16* d = (blockIdx.y == 0) ? d0 : (blockIdx.y == 1) ? d1 : (blockIdx.y == 2) ? d2 : d3;
    int i = blockIdx.x*blockDim.x + threadIdx.x;
    float4 v = ((const float4*)s)[i];
    __nv_bfloat162* d2p = (__nv_bfloat162*)d;
    d2p[2*i]   = __floats2bfloat162_rn(v.x, v.y);
    d2p[2*i+1] = __floats2bfloat162_rn(v.z, v.w);
}

// ---------------------------------------------------------------------------
// RMSNorm -> bf16 out
// ---------------------------------------------------------------------------
__global__ void rmsnorm_kernel(__nv_bfloat16* __restrict__ out, const float* __restrict__ x,
                               const float* __restrict__ w) {
    int row = blockIdx.x;
    int tid = threadIdx.x;
    float vx = x[row*DM + tid];
    float ss = vx*vx;
    #pragma unroll
    for (int off = 16; off >= 1; off >>= 1) ss += __shfl_xor_sync(0xffffffffu, ss, off);
    __shared__ float ws[8];
    if ((tid & 31) == 0) ws[tid >> 5] = ss;
    __syncthreads();
    float tot = ws[0];
    #pragma unroll
    for (int i = 1; i < 8; ++i) tot += ws[i];
    float rinv = rsqrtf(tot * (1.0f/DM) + 1e-5f);
    out[row*DM + tid] = __float2bfloat16_rn(vx * rinv * w[tid]);
}

// ---------------------------------------------------------------------------
// bf16 tensor-core GEMM: C[M,N] = A[M,K] @ Bw[N,K]^T (+res if fp32 out)
// 128 x BN_ tile, BK=64, 3-stage cp.async, 8 warps (4x2), ldmatrix b16
// OBF: true -> bf16 output (no residual), false -> fp32 output (+res)
// ---------------------------------------------------------------------------
#define TSTR 72   // bf16 units per smem row (64 + 8 pad)

template<int BN_, bool OBF>
__global__ __launch_bounds__(256, 2)
void gemm_bf16(const __nv_bfloat16* __restrict__ A,
               const __nv_bfloat16* __restrict__ B0, const __nv_bfloat16* __restrict__ B1,
               const __nv_bfloat16* __restrict__ B2,
               void* __restrict__ C0, void* __restrict__ C1, void* __restrict__ C2,
               const float* __restrict__ res,
               int M, int N, int K) {
    constexpr int WN  = BN_/16;
    constexpr int ASZ = 128*TSTR;
    constexpr int BSZ = BN_*TSTR;
    extern __shared__ __nv_bfloat16 smb[];
    __nv_bfloat16* As = smb;                  // 3 stages
    __nv_bfloat16* Bs = smb + 3*ASZ;

    const __nv_bfloat16* Bw = (blockIdx.z == 0) ? B0 : (blockIdx.z == 1 ? B1 : B2);
    void*                C  = (blockIdx.z == 0) ? C0 : (blockIdx.z == 1 ? C1 : C2);

    const int tid = threadIdx.x, lane = tid & 31, wid = tid >> 5;
    const int wrow = wid >> 1, wcol = wid & 1;
    const int row0 = blockIdx.y * 128;
    const int col0 = blockIdx.x * BN_;

    const int aoff = ((lane & 7) + ((lane >> 3) & 1)*8)*TSTR + (lane >> 4)*8;
    const int boff = ((lane & 7) + (lane >> 4)*8)*TSTR + ((lane >> 3) & 1)*8;

    float acc[2][WN][4];
    #pragma unroll
    for (int i = 0; i < 2; ++i)
        #pragma unroll
        for (int j = 0; j < WN; ++j)
            #pragma unroll
            for (int t = 0; t < 4; ++t) acc[i][j][t] = 0.f;

    auto load_stage = [&](int k0, int st) {
        __nv_bfloat16* as = As + st*ASZ;
        __nv_bfloat16* bs = Bs + st*BSZ;
        #pragma unroll
        for (int it = 0; it < 4; ++it) {
            int idx = it*256 + tid, r = idx >> 3, c8 = (idx & 7)*8;
            cpa16(as + r*TSTR + c8, A + (size_t)(row0 + r)*K + k0 + c8);
        }
        #pragma unroll
        for (int it = 0; it < BN_/32; ++it) {
            int idx = it*256 + tid, r = idx >> 3, c8 = (idx & 7)*8;
            cpa16(bs + r*TSTR + c8, Bw + (size_t)(col0 + r)*K + k0 + c8);
        }
        cp_commit();
    };

    const int nt = K / 64;
    load_stage(0, 0);
    load_stage(64, 1);
    for (int t = 0; t < nt; ++t) {
        if (t + 2 < nt)      { load_stage((t+2)*64, (t+2) % 3); cp_wait<2>(); }
        else if (t + 1 < nt) { cp_wait<1>(); }
        else                 { cp_wait<0>(); }
        __syncthreads();
        const __nv_bfloat16* as = As + (t % 3)*ASZ + aoff + wrow*32*TSTR;
        const __nv_bfloat16* bs = Bs + (t % 3)*BSZ + boff + wcol*(BN_/2)*TSTR;
        #pragma unroll
        for (int ks = 0; ks < 4; ++ks) {
            const int kk = ks*16;
            unsigned a[2][4], b[WN][2];
            #pragma unroll
            for (int i = 0; i < 2; ++i)
                ldsm4(a[i], as + i*16*TSTR + kk);
            #pragma unroll
            for (int jp = 0; jp < WN/2; ++jp)
                ldsm4(&b[2*jp][0], bs + jp*16*TSTR + kk);
            #pragma unroll
            for (int i = 0; i < 2; ++i)
                #pragma unroll
                for (int j = 0; j < WN; ++j)
                    mma_bf16(acc[i][j], a[i], b[j]);
        }
        __syncthreads();
    }

    #pragma unroll
    for (int i = 0; i < 2; ++i) {
        int r = row0 + wrow*32 + i*16 + (lane >> 2);
        #pragma unroll
        for (int j = 0; j < WN; ++j) {
            int c = col0 + wcol*(BN_/2) + j*8 + (lane & 3)*2;
            if (OBF) {
                __nv_bfloat16* Cb = (__nv_bfloat16*)C;
                *(unsigned*)(Cb + (size_t)r*N + c)     = pack_bf16(acc[i][j][0], acc[i][j][1]);
                *(unsigned*)(Cb + (size_t)(r+8)*N + c) = pack_bf16(acc[i][j][2], acc[i][j][3]);
            } else {
                float* Cf = (float*)C;
                float2 v01 = { acc[i][j][0], acc[i][j][1] };
                float2 v23 = { acc[i][j][2], acc[i][j][3] };
                if (res) {
                    float2 r01 = *(const float2*)(res + (size_t)r*N + c);
                    float2 r23 = *(const float2*)(res + (size_t)(r+8)*N + c);
                    v01.x += r01.x; v01.y += r01.y;
                    v23.x += r23.x; v23.y += r23.y;
                }
                *(float2*)(Cf + (size_t)r*N + c)     = v01;
                *(float2*)(Cf + (size_t)(r+8)*N + c) = v23;
            }
        }
    }
}

// ---------------------------------------------------------------------------
// Fused gate/up GEMM + SiLU (bf16): g = silu(A@Wg^T) * (A@Wu^T), bf16 out
// ---------------------------------------------------------------------------
__global__ __launch_bounds__(256, 2)
void gemm_gateup(const __nv_bfloat16* __restrict__ A,
                 const __nv_bfloat16* __restrict__ Wg, const __nv_bfloat16* __restrict__ Wu,
                 __nv_bfloat16* __restrict__ G, int M, int N, int K) {
    constexpr int ASZ = 128*TSTR;
    constexpr int BSZ = 64*TSTR;
    extern __shared__ __nv_bfloat16 smb[];
    __nv_bfloat16* As = smb;
    __nv_bfloat16* Gs = smb + 3*ASZ;
    __nv_bfloat16* Us = Gs + 3*BSZ;

    const int tid = threadIdx.x, lane = tid & 31, wid = tid >> 5;
    const int wrow = wid >> 1, wcol = wid & 1;
    const int row0 = blockIdx.y * 128;
    const int col0 = blockIdx.x * 64;

    const int aoff = ((lane & 7) + ((lane >> 3) & 1)*8)*TSTR + (lane >> 4)*8;
    const int boff = ((lane & 7) + (lane >> 4)*8)*TSTR + ((lane >> 3) & 1)*8;

    float accg[2][4][4], accu[2][4][4];
    #pragma unroll
    for (int i = 0; i < 2; ++i)
        #pragma unroll
        for (int j = 0; j < 4; ++j)
            #pragma unroll
            for (int t = 0; t < 4; ++t) { accg[i][j][t] = 0.f; accu[i][j][t] = 0.f; }

    auto load_stage = [&](int k0, int st) {
        __nv_bfloat16* as = As + st*ASZ;
        __nv_bfloat16* gs = Gs + st*BSZ;
        __nv_bfloat16* us = Us + st*BSZ;
        #pragma unroll
        for (int it = 0; it < 4; ++it) {
            int idx = it*256 + tid, r = idx >> 3, c8 = (idx & 7)*8;
            cpa16(as + r*TSTR + c8, A + (size_t)(row0 + r)*K + k0 + c8);
        }
        #pragma unroll
        for (int it = 0; it < 2; ++it) {
            int idx = it*256 + tid, r = idx >> 3, c8 = (idx & 7)*8;
            cpa16(gs + r*TSTR + c8, Wg + (size_t)(col0 + r)*K + k0 + c8);
            cpa16(us + r*TSTR + c8, Wu + (size_t)(col0 + r)*K + k0 + c8);
        }
        cp_commit();
    };

    const int nt = K / 64;
    load_stage(0, 0);
    load_stage(64, 1);
    for (int t = 0; t < nt; ++t) {
        if (t + 2 < nt)      { load_stage((t+2)*64, (t+2) % 3); cp_wait<2>(); }
        else if (t + 1 < nt) { cp_wait<1>(); }
        else                 { cp_wait<0>(); }
        __syncthreads();
        const __nv_bfloat16* as = As + (t % 3)*ASZ + aoff + wrow*32*TSTR;
        const __nv_bfloat16* gs = Gs + (t % 3)*BSZ + boff + wcol*32*TSTR;
        const __nv_bfloat16* us = Us + (t % 3)*BSZ + boff + wcol*32*TSTR;
        #pragma unroll
        for (int ks = 0; ks < 4; ++ks) {
            const int kk = ks*16;
            unsigned a[2][4], bg[4][2], bu[4][2];
            #pragma unroll
            for (int i = 0; i < 2; ++i)
                ldsm4(a[i], as + i*16*TSTR + kk);
            #pragma unroll
            for (int jp = 0; jp < 2; ++jp) {
                ldsm4(&bg[2*jp][0], gs + jp*16*TSTR + kk);
                ldsm4(&bu[2*jp][0], us + jp*16*TSTR + kk);
            }
            #pragma unroll
            for (int i = 0; i < 2; ++i)
                #pragma unroll
                for (int j = 0; j < 4; ++j) {
                    mma_bf16(accg[i][j], a[i], bg[j]);
                    mma_bf16(accu[i][j], a[i], bu[j]);
                }
        }
        __syncthreads();
    }

    #pragma unroll
    for (int i = 0; i < 2; ++i) {
        int r = row0 + wrow*32 + i*16 + (lane >> 2);
        #pragma unroll
        for (int j = 0; j < 4; ++j) {
            int c = col0 + wcol*32 + j*8 + (lane & 3)*2;
            float g0 = accg[i][j][0], g1 = accg[i][j][1];
            float g2 = accg[i][j][2], g3 = accg[i][j][3];
            float p0 = g0 / (1.f + __expf(-g0)) * accu[i][j][0];
            float p1 = g1 / (1.f + __expf(-g1)) * accu[i][j][1];
            float p2 = g2 / (1.f + __expf(-g2)) * accu[i][j][2];
            float p3 = g3 / (1.f + __expf(-g3)) * accu[i][j][3];
            *(unsigned*)(G + (size_t)r*N + c)     = pack_bf16(p0, p1);
            *(unsigned*)(G + (size_t)(r+8)*N + c) = pack_bf16(p2, p3);
        }
    }
}

// ---------------------------------------------------------------------------
// bf16 tensor-core flash attention, double-buffered K/V, occ 4
// 512 blocks (16 bh x 32 q-tiles of 64 rows, heavy-first), 128 threads
// ---------------------------------------------------------------------------
#define QSTR 72
#define KSTR 72
#define VSTR 72

__global__ __launch_bounds__(128, 4)
void attn_bf16(__nv_bfloat16* __restrict__ out, const __nv_bfloat16* __restrict__ q,
               const __nv_bfloat16* __restrict__ k, const __nv_bfloat16* __restrict__ v) {
    extern __shared__ __nv_bfloat16 smb[];
    __nv_bfloat16* Qs = smb;                    // 64 x QSTR
    __nv_bfloat16* Ks = Qs + 64*QSTR;           // 2 stages 64 x KSTR
    __nv_bfloat16* Vs = Ks + 2*64*KSTR;         // 2 stages 64 x VSTR

    const int tid = threadIdx.x, lane = tid & 31, wid = tid >> 5;
    const int bh = blockIdx.x;
    const int qx = 31 - blockIdx.y;             // heavy tiles first
    const int b = bh >> 2, h = bh & 3;
    const int q0 = qx * 64;
    const int ntile = qx + 1;
    const size_t base = (size_t)b*TT*DM + (size_t)h*DK;

    const int r0l = wid*16 + (lane >> 2);
    const float sc = 0.125f;

    // ldmatrix lane offsets (A-pattern also serves V-trans)
    const int aoff = ((lane & 7) + ((lane >> 3) & 1)*8)*QSTR + (lane >> 4)*8;
    const int koff = ((lane & 7) + (lane >> 4)*8)*KSTR + ((lane >> 3) & 1)*8;
    const int voff = ((lane & 7) + ((lane >> 3) & 1)*8)*VSTR + (lane >> 4)*8;

    auto load_kv = [&](int jt, int st) {
        const int k0 = jt*64;
        __nv_bfloat16* ks_ = Ks + st*64*KSTR;
        __nv_bfloat16* vs_ = Vs + st*64*VSTR;
        #pragma unroll
        for (int it = 0; it < 4; ++it) {
            int idx = it*128 + tid, r = idx >> 3, c8 = (idx & 7)*8;
            cpa16(ks_ + r*KSTR + c8, k + base + (size_t)(k0 + r)*DM + c8);
            cpa16(vs_ + r*VSTR + c8, v + base + (size_t)(k0 + r)*DM + c8);
        }
        cp_commit();
    };

    // Q tile + first KV stage
    #pragma unroll
    for (int it = 0; it < 4; ++it) {
        int idx = it*128 + tid, r = idx >> 3, c8 = (idx & 7)*8;
        cpa16(Qs + r*QSTR + c8, q + base + (size_t)(q0 + r)*DM + c8);
    }
    cp_commit();
    load_kv(0, 0);

    float o[8][4];
    #pragma unroll
    for (int j = 0; j < 8; ++j)
        #pragma unroll
        for (int t = 0; t < 4; ++t) o[j][t] = 0.f;
    float m0 = -1e30f, m1 = -1e30f, l0 = 0.f, l1 = 0.f;

    for (int jt = 0; jt < ntile; ++jt) {
        if (jt + 1 < ntile) { load_kv(jt+1, (jt+1) & 1); cp_wait<1>(); }
        else                { cp_wait<0>(); }
        __syncthreads();
        const __nv_bfloat16* ks_ = Ks + (jt & 1)*64*KSTR;
        const __nv_bfloat16* vs_ = Vs + (jt & 1)*64*VSTR;
        const int k0 = jt*64;

        // ---- S = Q @ K^T : 4 k16 steps, 8 n-tiles ----
        float s[8][4];
        #pragma unroll
        for (int j = 0; j < 8; ++j)
            #pragma unroll
            for (int t = 0; t < 4; ++t) s[j][t] = 0.f;
        #pragma unroll
        for (int ks = 0; ks < 4; ++ks) {
            const int kk = ks*16;
            unsigned aq[4], bv[8][2];
            ldsm4(aq, Qs + wid*16*QSTR + aoff + kk);
            #pragma unroll
            for (int jp = 0; jp < 4; ++jp)
                ldsm4(&bv[2*jp][0], ks_ + jp*16*KSTR + koff + kk);
            #pragma unroll
            for (int j = 0; j < 8; ++j)
                mma_bf16(s[j], aq, bv[j]);
        }

        // ---- causal mask (diagonal tile only) ----
        if (jt == ntile - 1) {
            const int row_a = q0 + r0l, row_b = row_a + 8;
            #pragma unroll
            for (int j = 0; j < 8; ++j) {
                int col = k0 + j*8 + 2*(lane & 3);
                if (col     > row_a) s[j][0] = -1e30f;
                if (col + 1 > row_a) s[j][1] = -1e30f;
                if (col     > row_b) s[j][2] = -1e30f;
                if (col + 1 > row_b) s[j][3] = -1e30f;
            }
        }

        // ---- online softmax ----
        float mx0 = -1e30f, mx1 = -1e30f;
        #pragma unroll
        for (int j = 0; j < 8; ++j) {
            mx0 = fmaxf(mx0, fmaxf(s[j][0], s[j][1]));
            mx1 = fmaxf(mx1, fmaxf(s[j][2], s[j][3]));
        }
        #pragma unroll
        for (int off = 1; off <= 2; off <<= 1) {
            mx0 = fmaxf(mx0, __shfl_xor_sync(0xffffffffu, mx0, off));
            mx1 = fmaxf(mx1, __shfl_xor_sync(0xffffffffu, mx1, off));
        }
        float mn0 = fmaxf(m0, mx0), mn1 = fmaxf(m1, mx1);
        float al0 = __expf((m0 - mn0)*sc), al1 = __expf((m1 - mn1)*sc);
        m0 = mn0; m1 = mn1;
        float rs0 = 0.f, rs1 = 0.f;
        #pragma unroll
        for (int j = 0; j < 8; ++j) {
            s[j][0] = __expf((s[j][0] - mn0)*sc); rs0 += s[j][0];
            s[j][1] = __expf((s[j][1] - mn0)*sc); rs0 += s[j][1];
            s[j][2] = __expf((s[j][2] - mn1)*sc); rs1 += s[j][2];
            s[j][3] = __expf((s[j][3] - mn1)*sc); rs1 += s[j][3];
        }
        #pragma unroll
        for (int off = 1; off <= 2; off <<= 1) {
            rs0 += __shfl_xor_sync(0xffffffffu, rs0, off);
            rs1 += __shfl_xor_sync(0xffffffffu, rs1, off);
        }
        l0 = l0*al0 + rs0;
        l1 = l1*al1 + rs1;

        // ---- O = O*alpha + P @ V (P packs directly to bf16 A-fragments) ----
        #pragma unroll
        for (int j = 0; j < 8; ++j) {
            o[j][0] *= al0; o[j][1] *= al0;
            o[j][2] *= al1; o[j][3] *= al1;
        }
        #pragma unroll
        for (int kb = 0; kb < 4; ++kb) {
            unsigned ap[4];
            ap[0] = pack_bf16(s[2*kb  ][0], s[2*kb  ][1]);
            ap[1] = pack_bf16(s[2*kb  ][2], s[2*kb  ][3]);
            ap[2] = pack_bf16(s[2*kb+1][0], s[2*kb+1][1]);
            ap[3] = pack_bf16(s[2*kb+1][2], s[2*kb+1][3]);
            const int kk = kb*16;
            unsigned bv[8][2];
            #pragma unroll
            for (int jp = 0; jp < 4; ++jp)
                ldsm4t(&bv[2*jp][0], vs_ + kk*VSTR + voff + jp*16);
            #pragma unroll
            for (int j = 0; j < 8; ++j)
                mma_bf16(o[j], ap, bv[j]);
        }
        __syncthreads();                // all reads of this stage done
    }

    // ---- epilogue (bf16 out) ----
    const float inv0 = 1.f / l0, inv1 = 1.f / l1;
    const int grow = q0 + r0l;
    #pragma unroll
    for (int j = 0; j < 8; ++j) {
        int cc = j*8 + 2*(lane & 3);
        *(unsigned*)(out + base + (size_t)grow*DM + cc) =
            pack_bf16(o[j][0]*inv0, o[j][1]*inv0);
        *(unsigned*)(out + base + (size_t)(grow + 8)*DM + cc) =
            pack_bf16(o[j][2]*inv1, o[j][3]*inv1);
    }
}

// ---------------------------------------------------------------------------
// Launch
// ---------------------------------------------------------------------------
extern "C" void kernel_launch(void* const* d_in, const int* in_sizes, int n_in,
                              void* d_out, int out_size) {
    const float* x        = (const float*)d_in[0];
    const float* rms_attn = (const float*)d_in[2];
    const float* wq       = (const float*)d_in[3];
    const float* wk       = (const float*)d_in[4];
    const float* wv       = (const float*)d_in[5];
    const float* wo       = (const float*)d_in[6];
    const float* rms_ffn  = (const float*)d_in[7];
    const float* w_gate   = (const float*)d_in[8];
    const float* w_up     = (const float*)d_in[9];
    const float* w_down   = (const float*)d_in[10];
    float* out = (float*)d_out;

    __nv_bfloat16 *h, *q, *k, *v, *attn, *hf, *gate;
    __nv_bfloat16 *bwq, *bwk, *bwv, *bwo, *bwg, *bwu, *bwd;
    float *x1;
    cudaGetSymbolAddress((void**)&h,    gb_h);
    cudaGetSymbolAddress((void**)&q,    gb_q);
    cudaGetSymbolAddress((void**)&k,    gb_k);
    cudaGetSymbolAddress((void**)&v,    gb_v);
    cudaGetSymbolAddress((void**)&attn, gb_attn);
    cudaGetSymbolAddress((void**)&hf,   gb_hf);
    cudaGetSymbolAddress((void**)&gate, gb_gate);
    cudaGetSymbolAddress((void**)&x1,   g_x1);
    cudaGetSymbolAddress((void**)&bwq,  gb_wq);
    cudaGetSymbolAddress((void**)&bwk,  gb_wk);
    cudaGetSymbolAddress((void**)&bwv,  gb_wv);
    cudaGetSymbolAddress((void**)&bwo,  gb_wo);
    cudaGetSymbolAddress((void**)&bwg,  gb_wg);
    cudaGetSymbolAddress((void**)&bwu,  gb_wu);
    cudaGetSymbolAddress((void**)&bwd,  gb_wd);

    const int GS128 = 3*(128 + 128)*TSTR*2;                 // 110592 B
    const int GS64  = 3*(128 +  64)*TSTR*2;                 // 82944 B
    const int GSGU  = 3*(128 + 64 + 64)*TSTR*2;             // 110592 B
    const int ASM   = (64*QSTR + 2*64*KSTR + 2*64*VSTR)*2;  // 46080 B
    cudaFuncSetAttribute((const void*)gemm_bf16<128,true>,  cudaFuncAttributeMaxDynamicSharedMemorySize, GS128);
    cudaFuncSetAttribute((const void*)gemm_bf16<64,false>,  cudaFuncAttributeMaxDynamicSharedMemorySize, GS64);
    cudaFuncSetAttribute((const void*)gemm_gateup,          cudaFuncAttributeMaxDynamicSharedMemorySize, GSGU);
    cudaFuncSetAttribute((const void*)attn_bf16,            cudaFuncAttributeMaxDynamicSharedMemorySize, ASM);

    // 0. convert weights to bf16
    conv4<<<dim3(DM*DM/1024, 4), 256>>>(wq, wk, wv, wo, bwq, bwk, bwv, bwo);
    conv4<<<dim3(DFF*DM/1024, 3), 256>>>(w_gate, w_up, w_down, w_down, bwg, bwu, bwd, bwd);

    // 1. h = rmsnorm(x) -> bf16
    rmsnorm_kernel<<<BT, 256>>>(h, x, rms_attn);

    // 2. fused q,k,v projections -> bf16
    gemm_bf16<128,true><<<dim3(DM/128, BT/128, 3), 256, GS128>>>(
        h, bwq, bwk, bwv, q, k, v, nullptr, BT, DM, DM);

    // 3. attention -> bf16
    attn_bf16<<<dim3(BB*NH, 32), 128, ASM>>>(attn, q, k, v);

    // 4. x1 = x + attn @ wo^T  (fp32)
    gemm_bf16<64,false><<<dim3(DM/64, BT/128, 1), 256, GS64>>>(
        attn, bwo, bwo, bwo, x1, x1, x1, x, BT, DM, DM);

    // 5. hf = rmsnorm(x1) -> bf16
    rmsnorm_kernel<<<BT, 256>>>(hf, x1, rms_ffn);

    // 6. fused gate/up/silu -> bf16
    gemm_gateup<<<dim3(DFF/64, BT/128), 256, GSGU>>>(
        hf, bwg, bwu, gate, BT, DFF, DM);

    // 7. out = x1 + gate @ w_down^T  (fp32)
    gemm_bf16<64,false><<<dim3(DM/64, BT/128, 1), 256, GS64>>>(
        gate, bwd, bwd, bwd, out, out, out, x1, BT, DM, DFF);
}